// round 9
// baseline (speedup 1.0000x reference)
#include <cuda_runtime.h>
#include <cstdint>

// Problem constants (fixed shapes from reference)
#define BB 8
#define NVV 8192
#define EE 32768

typedef unsigned long long ull;

// Scratch (no cudaMalloc allowed)
// g_M is TRANSPOSED: g_M[bc][e], bc = b*3+c  -> contiguous in e
__device__ float g_M[24 * EE];       // 3 MB
__device__ float g_Lv[24 * NVV];     // 768 KB: Lv[bc][n]

// ---------------------------------------------------------------------------
// Kernel 0: zero the L_vert accumulator
// ---------------------------------------------------------------------------
__global__ void k_zero() {
    int t = blockIdx.x * blockDim.x + threadIdx.x;
    if (t < 24 * NVV) g_Lv[t] = 0.0f;
}

// ---------------------------------------------------------------------------
// Kernel 1: per-(b,e) constraint solve -> L_new + transposed M scratch
// ---------------------------------------------------------------------------
__global__ void k_edge(const float* __restrict__ Vp,     // (B,NV,3)
                       const float* __restrict__ L,      // (B,E,1)
                       const float* __restrict__ Vw,     // (B,NV,1)
                       const float* __restrict__ Vc,     // (B,1,1)
                       const int*   __restrict__ Cd,     // (E,2)
                       const float* __restrict__ Cid,    // (E,1)
                       float*       __restrict__ Lnew)   // (B,E) at d_out + B*NV*3
{
    int tid = blockIdx.x * blockDim.x + threadIdx.x;
    if (tid >= BB * EE) return;
    int b = tid / EE;
    int e = tid - b * EE;

    int i = Cd[2 * e];
    int j = Cd[2 * e + 1];

    const float* pi = Vp + ((size_t)b * NVV + i) * 3;
    const float* pj = Vp + ((size_t)b * NVV + j) * 3;
    float nx = pi[0] - pj[0];
    float ny = pi[1] - pj[1];
    float nz = pi[2] - pj[2];
    float D = sqrtf(nx * nx + ny * ny + nz * nz);
    float C = D - Cid[e];

    float A = Vc[b];
    float S = Vw[b * NVV + i] + Vw[b * NVV + j];
    float Seff = (S == 0.0f) ? __int_as_float(0x7f800000) : S;   // inf where S==0
    float denom = Seff + A;

    float l  = L[tid];                  // L is (B,E) contiguous, tid = b*E+e
    float ld = (-C - A * l) / denom;    // -> 0 when denom == inf
    Lnew[tid] = l + ld;

    float inv = ld / (D + 1e-8f);       // L_delta * N_norm
    // transposed, coalesced over e
    g_M[(size_t)(b * 3 + 0) * EE + e] = inv * nx;
    g_M[(size_t)(b * 3 + 1) * EE + e] = inv * ny;
    g_M[(size_t)(b * 3 + 2) * EE + e] = inv * nz;
}

// ---------------------------------------------------------------------------
// Kernel 2: Lv[bc][n] = sum_e M[bc][e] * C_mtx[e][n]
//
// v3: f32x2 halves packed along E (even-e / odd-e partial sums of the SAME
// column) instead of along N:
//  - M tile staged in SMEM transposed [bc][e], NO duplication ->
//    one LDS.128 = m[e0..e3][bc] = TWO FFMA2 operands (6 LDS/e vs 12)
//  - cv transpose: 2 row-loads repacked into (c[e0][n],c[e1][n]) pairs via
//    cheap ALU ops (alu pipe was idle)
//  - lo+hi halves merge BEFORE the atomic -> 12.5M lane-REDs (was 25M)
//  - one-group-ahead software prefetch of cv (distance >> DRAM latency)
//  - persistent grid 444 = 148 SMs x 3 blocks (__launch_bounds__(128,3)),
//    4096 fine work items -> ~9.2 items/block
// ---------------------------------------------------------------------------
#define GT 128                       // threads per block
#define TILE_N 256                   // 2 columns per thread
#define E_TILE 64                    // e rows staged per barrier
#define E_CHUNK 256                  // e rows per work item
#define N_BLKS (NVV / TILE_N)        // 32
#define E_BLKS (EE / E_CHUNK)        // 128
#define N_ITEMS (N_BLKS * E_BLKS)    // 4096
#define GRID_G 444                   // 148 SMs * 3 blocks

__global__ void __launch_bounds__(GT, 3)
k_gemm(const float* __restrict__ Cm)   // C_mtx (E, NV) row-major
{
    __shared__ float Msf[24 * E_TILE];   // transposed tile: [bc][e], 6 KB

    const int t = threadIdx.x;

    for (int item = blockIdx.x; item < N_ITEMS; item += GRID_G) {
        const int nb = item & (N_BLKS - 1);
        const int eb = item >> 5;                 // item / N_BLKS
        const int n0 = nb * TILE_N + t * 2;
        const int e0 = eb * E_CHUNK;

        ull acc[48];                  // acc[bc*2+c]: (sum_even_e, sum_odd_e) of col n0+c
#pragma unroll
        for (int k = 0; k < 48; k++) acc[k] = 0ull;

        for (int et = 0; et < E_CHUNK; et += E_TILE) {
            // Stage transposed M tile: Msf[bc*64+ee] = g_M[bc*EE + (e0+et)+ee]
            {
                const size_t e_g = (size_t)(e0 + et);
#pragma unroll
                for (int i = 0; i < 3; i++) {
                    int k = (i * GT + t) * 4;             // 0..1532, 16B steps
                    int bc = k >> 6, ee = k & 63;
                    float4 v = *reinterpret_cast<const float4*>(
                        g_M + (size_t)bc * EE + e_g + ee);
                    *reinterpret_cast<float4*>(Msf + k) = v;
                }
            }
            __syncthreads();

            const float* p = Cm + (size_t)(e0 + et) * NVV + n0;
            // prefetch group 0 (4 e-rows)
            ull a0 = __ldcs(reinterpret_cast<const ull*>(p));
            ull a1 = __ldcs(reinterpret_cast<const ull*>(p + NVV));
            ull a2 = __ldcs(reinterpret_cast<const ull*>(p + 2 * NVV));
            ull a3 = __ldcs(reinterpret_cast<const ull*>(p + 3 * NVV));
            p += 4 * NVV;

#pragma unroll
            for (int g = 0; g < E_TILE / 4; g++) {
                ull b0 = 0, b1 = 0, b2 = 0, b3 = 0;
                if (g + 1 < E_TILE / 4) {           // prefetch next group
                    b0 = __ldcs(reinterpret_cast<const ull*>(p));
                    b1 = __ldcs(reinterpret_cast<const ull*>(p + NVV));
                    b2 = __ldcs(reinterpret_cast<const ull*>(p + 2 * NVV));
                    b3 = __ldcs(reinterpret_cast<const ull*>(p + 3 * NVV));
                    p += 4 * NVV;
                }
                // transpose to e-pairs:
                // p0=(c[e0][n],c[e1][n])  p1=(c[e0][n'],c[e1][n'])
                // p2=(c[e2][n],c[e3][n])  p3=(c[e2][n'],c[e3][n'])
                ull p0 = (a0 & 0xffffffffull) | (a1 << 32);
                ull p1 = (a0 >> 32) | (a1 & 0xffffffff00000000ull);
                ull p2 = (a2 & 0xffffffffull) | (a3 << 32);
                ull p3 = (a2 >> 32) | (a3 & 0xffffffff00000000ull);

                const float* ms = Msf + g * 4;
#pragma unroll
                for (int bc = 0; bc < 24; bc++) {
                    // LDS.128: m[e0..e3][bc] -> two f32x2 operands, no dup
                    ulonglong2 mm = *reinterpret_cast<const ulonglong2*>(
                        ms + bc * E_TILE);
                    asm("fma.rn.f32x2 %0, %1, %2, %0;"
                        : "+l"(acc[bc * 2 + 0]) : "l"(mm.x), "l"(p0));
                    asm("fma.rn.f32x2 %0, %1, %2, %0;"
                        : "+l"(acc[bc * 2 + 1]) : "l"(mm.x), "l"(p1));
                    asm("fma.rn.f32x2 %0, %1, %2, %0;"
                        : "+l"(acc[bc * 2 + 0]) : "l"(mm.y), "l"(p2));
                    asm("fma.rn.f32x2 %0, %1, %2, %0;"
                        : "+l"(acc[bc * 2 + 1]) : "l"(mm.y), "l"(p3));
                }
                a0 = b0; a1 = b1; a2 = b2; a3 = b3;
            }
            __syncthreads();
        }

        // merge even/odd halves, then one RED per (bc, col)
#pragma unroll
        for (int bc = 0; bc < 24; bc++) {
            float* dst = g_Lv + (size_t)bc * NVV + n0;
            ull s0 = acc[bc * 2 + 0];
            ull s1 = acc[bc * 2 + 1];
            atomicAdd(dst + 0, __uint_as_float((unsigned)(s0 & 0xffffffffu)) +
                               __uint_as_float((unsigned)(s0 >> 32)));
            atomicAdd(dst + 1, __uint_as_float((unsigned)(s1 & 0xffffffffu)) +
                               __uint_as_float((unsigned)(s1 >> 32)));
        }
    }
}

// ---------------------------------------------------------------------------
// Kernel 3: V_predict_new = V_predict + V_w * L_vert
// ---------------------------------------------------------------------------
__global__ void k_epi(const float* __restrict__ Vp,
                      const float* __restrict__ Vw,
                      float*       __restrict__ out)     // (B,NV,3) at d_out
{
    int tid = blockIdx.x * blockDim.x + threadIdx.x;
    if (tid >= BB * NVV) return;
    int b = tid / NVV;
    int n = tid - b * NVV;
    float w = Vw[tid];
    size_t o = (size_t)tid * 3;
    out[o + 0] = Vp[o + 0] + w * g_Lv[(size_t)(b * 3 + 0) * NVV + n];
    out[o + 1] = Vp[o + 1] + w * g_Lv[(size_t)(b * 3 + 1) * NVV + n];
    out[o + 2] = Vp[o + 2] + w * g_Lv[(size_t)(b * 3 + 2) * NVV + n];
}

// ---------------------------------------------------------------------------
extern "C" void kernel_launch(void* const* d_in, const int* in_sizes, int n_in,
                              void* d_out, int out_size)
{
    const float* Vp  = (const float*)d_in[0];   // V_predict    (B,NV,3)
    const float* L   = (const float*)d_in[1];   // L            (B,E,1)
    const float* Vw  = (const float*)d_in[2];   // V_w          (B,NV,1)
    const float* Vc  = (const float*)d_in[3];   // V_compliance (B,1,1)
    const int*   Cd  = (const int*)  d_in[4];   // C_dist       (E,2)
    const float* Cid = (const float*)d_in[5];   // C_init_d     (E,1)
    const float* Cm  = (const float*)d_in[6];   // C_mtx        (E,NV)

    float* out_vp = (float*)d_out;                         // V_predict_new
    float* out_L  = (float*)d_out + (size_t)BB * NVV * 3;  // L_new

    // 0) zero accumulator
    k_zero<<<(24 * NVV + 255) / 256, 256>>>();

    // 1) edge solve -> transposed M, L_new
    k_edge<<<(BB * EE + 255) / 256, 256>>>(Vp, L, Vw, Vc, Cd, Cid, out_L);

    // 2) tall-skinny GEMM: Lv = M @ C_mtx  (persistent, single wave)
    k_gemm<<<GRID_G, GT>>>(Cm);

    // 3) vertex update
    k_epi<<<(BB * NVV + 255) / 256, 256>>>(Vp, Vw, out_vp);
}

// round 10
// speedup vs baseline: 1.5333x; 1.5333x over previous
#include <cuda_runtime.h>
#include <cstdint>

// Problem constants (fixed shapes from reference)
#define BB 8
#define NVV 8192
#define EE 32768

typedef unsigned long long ull;

// Scratch (no cudaMalloc allowed): M in (e, bc) layout + L_vert accumulator
__device__ float g_M[EE * 24];       // 3 MB:  M[e][b*3+c]
__device__ float g_Lv[24 * NVV];     // 768 KB: Lv[bc][n]

// ---------------------------------------------------------------------------
// Kernel 0: zero the L_vert accumulator
// ---------------------------------------------------------------------------
__global__ void k_zero() {
    int t = blockIdx.x * blockDim.x + threadIdx.x;
    if (t < 24 * NVV) g_Lv[t] = 0.0f;
}

// ---------------------------------------------------------------------------
// Kernel 1: per-(b,e) constraint solve -> L_new + M scratch
// ---------------------------------------------------------------------------
__global__ void k_edge(const float* __restrict__ Vp,     // (B,NV,3)
                       const float* __restrict__ L,      // (B,E,1)
                       const float* __restrict__ Vw,     // (B,NV,1)
                       const float* __restrict__ Vc,     // (B,1,1)
                       const int*   __restrict__ Cd,     // (E,2)
                       const float* __restrict__ Cid,    // (E,1)
                       float*       __restrict__ Lnew)   // (B,E) at d_out + B*NV*3
{
    int tid = blockIdx.x * blockDim.x + threadIdx.x;
    if (tid >= BB * EE) return;
    int b = tid / EE;
    int e = tid - b * EE;

    int i = Cd[2 * e];
    int j = Cd[2 * e + 1];

    const float* pi = Vp + ((size_t)b * NVV + i) * 3;
    const float* pj = Vp + ((size_t)b * NVV + j) * 3;
    float nx = pi[0] - pj[0];
    float ny = pi[1] - pj[1];
    float nz = pi[2] - pj[2];
    float D = sqrtf(nx * nx + ny * ny + nz * nz);
    float C = D - Cid[e];

    float A = Vc[b];
    float S = Vw[b * NVV + i] + Vw[b * NVV + j];
    float Seff = (S == 0.0f) ? __int_as_float(0x7f800000) : S;   // inf where S==0
    float denom = Seff + A;

    float l  = L[tid];                  // L is (B,E) contiguous, tid = b*E+e
    float ld = (-C - A * l) / denom;    // -> 0 when denom == inf
    Lnew[tid] = l + ld;

    float inv = ld / (D + 1e-8f);       // L_delta * N_norm
    int mb = e * 24 + b * 3;
    g_M[mb + 0] = inv * nx;
    g_M[mb + 1] = inv * ny;
    g_M[mb + 2] = inv * nz;
}

// ---------------------------------------------------------------------------
// Kernel 2: Lv[bc][n] = sum_e M[e][bc] * C_mtx[e][n]
//
// v4 (R8 dataflow + three fixes):
//  - 4 columns/thread: per e = 48 FFMA2 vs 13 LSU ops -> fma-pipe-bound,
//    and 16B LDG.128 per thread doubles bytes-in-flight per load.
//  - explicit 1-group-ahead prefetch of two C rows (hides DRAM latency
//    together with 3 warps/SMSP at occupancy 3).
//  - CONTIGUOUS static work partition ordered nb-major: a block's items
//    share one n-block, accumulators persist across e-chunks, atomics flush
//    only on nb change (~475 flushes total vs 1 per item -> 4x fewer REDs).
// ---------------------------------------------------------------------------
#define GT 128                       // threads per block
#define COLS_PT 4
#define TILE_N (GT * COLS_PT)        // 512 columns per block
#define E_TILE 64                    // e rows staged per barrier
#define E_CHUNK 256                  // e rows per work item
#define N_BLKS (NVV / TILE_N)        // 16
#define E_BLKS (EE / E_CHUNK)        // 128
#define N_ITEMS (N_BLKS * E_BLKS)    // 2048, item = nb*E_BLKS + eb (nb-major)
#define GRID_G 444                   // 148 SMs * 3 blocks

__device__ __forceinline__ void flush_acc(const ull* acc, int nb, int t) {
    int n0 = nb * TILE_N + t * COLS_PT;
#pragma unroll
    for (int bc = 0; bc < 24; bc++) {
        float* dst = g_Lv + (size_t)bc * NVV + n0;
        ull s0 = acc[2 * bc + 0];     // cols n0, n0+1
        ull s1 = acc[2 * bc + 1];     // cols n0+2, n0+3
        atomicAdd(dst + 0, __uint_as_float((unsigned)(s0 & 0xffffffffu)));
        atomicAdd(dst + 1, __uint_as_float((unsigned)(s0 >> 32)));
        atomicAdd(dst + 2, __uint_as_float((unsigned)(s1 & 0xffffffffu)));
        atomicAdd(dst + 3, __uint_as_float((unsigned)(s1 >> 32)));
    }
}

__global__ void __launch_bounds__(GT, 3)
k_gemm(const float* __restrict__ Cm)   // C_mtx (E, NV) row-major
{
    __shared__ ull Ms[E_TILE][24];     // (m,m) duplicated pairs, 12 KB

    const int t = threadIdx.x;
    const int g = blockIdx.x;

    // contiguous slice of items for this block (q=4, r=272 at these sizes)
    const int q = N_ITEMS / GRID_G;
    const int r = N_ITEMS - q * GRID_G;
    const int start = g * q + (g < r ? g : r);
    const int count = q + (g < r ? 1 : 0);

    ull acc[48];
    int cur_nb = -1;

    for (int it = 0; it < count; it++) {
        const int item = start + it;
        const int nb = item >> 7;                 // item / E_BLKS
        const int eb = item & (E_BLKS - 1);

        if (nb != cur_nb) {
            if (cur_nb >= 0) flush_acc(acc, cur_nb, t);
#pragma unroll
            for (int k = 0; k < 48; k++) acc[k] = 0ull;
            cur_nb = nb;
        }

        const int n0 = nb * TILE_N + t * COLS_PT;
        const int e0 = eb * E_CHUNK;

        for (int et = 0; et < E_CHUNK; et += E_TILE) {
            // Stage E_TILE*24 M values as duplicated f32x2 pairs (coalesced)
            const float* msrc = g_M + (size_t)(e0 + et) * 24;
#pragma unroll
            for (int k = t; k < E_TILE * 24; k += GT) {
                ull d = (ull)__float_as_uint(msrc[k]);
                d |= d << 32;
                ((ull*)Ms)[k] = d;
            }
            __syncthreads();

            const float* p = Cm + (size_t)(e0 + et) * NVV + n0;
            // prefetch group 0 (2 e-rows, 16B each)
            ulonglong2 a0 = __ldcs(reinterpret_cast<const ulonglong2*>(p));
            ulonglong2 a1 = __ldcs(reinterpret_cast<const ulonglong2*>(p + NVV));
            p += 2 * NVV;

#pragma unroll 4
            for (int gg = 0; gg < E_TILE / 2; gg++) {
                ulonglong2 b0 = a0, b1 = a1;
                if (gg + 1 < E_TILE / 2) {        // prefetch next group
                    b0 = __ldcs(reinterpret_cast<const ulonglong2*>(p));
                    b1 = __ldcs(reinterpret_cast<const ulonglong2*>(p + NVV));
                    p += 2 * NVV;
                }
                const ull* m0 = &Ms[2 * gg + 0][0];
                const ull* m1 = &Ms[2 * gg + 1][0];
#pragma unroll
                for (int bc = 0; bc < 24; bc += 2) {
                    ulonglong2 mm0 = *reinterpret_cast<const ulonglong2*>(m0 + bc);
                    asm("fma.rn.f32x2 %0, %1, %2, %0;"
                        : "+l"(acc[2 * bc + 0]) : "l"(mm0.x), "l"(a0.x));
                    asm("fma.rn.f32x2 %0, %1, %2, %0;"
                        : "+l"(acc[2 * bc + 1]) : "l"(mm0.x), "l"(a0.y));
                    asm("fma.rn.f32x2 %0, %1, %2, %0;"
                        : "+l"(acc[2 * bc + 2]) : "l"(mm0.y), "l"(a0.x));
                    asm("fma.rn.f32x2 %0, %1, %2, %0;"
                        : "+l"(acc[2 * bc + 3]) : "l"(mm0.y), "l"(a0.y));
                    ulonglong2 mm1 = *reinterpret_cast<const ulonglong2*>(m1 + bc);
                    asm("fma.rn.f32x2 %0, %1, %2, %0;"
                        : "+l"(acc[2 * bc + 0]) : "l"(mm1.x), "l"(a1.x));
                    asm("fma.rn.f32x2 %0, %1, %2, %0;"
                        : "+l"(acc[2 * bc + 1]) : "l"(mm1.x), "l"(a1.y));
                    asm("fma.rn.f32x2 %0, %1, %2, %0;"
                        : "+l"(acc[2 * bc + 2]) : "l"(mm1.y), "l"(a1.x));
                    asm("fma.rn.f32x2 %0, %1, %2, %0;"
                        : "+l"(acc[2 * bc + 3]) : "l"(mm1.y), "l"(a1.y));
                }
                a0 = b0; a1 = b1;
            }
            __syncthreads();
        }
    }
    if (cur_nb >= 0) flush_acc(acc, cur_nb, t);
}

// ---------------------------------------------------------------------------
// Kernel 3: V_predict_new = V_predict + V_w * L_vert
// ---------------------------------------------------------------------------
__global__ void k_epi(const float* __restrict__ Vp,
                      const float* __restrict__ Vw,
                      float*       __restrict__ out)     // (B,NV,3) at d_out
{
    int tid = blockIdx.x * blockDim.x + threadIdx.x;
    if (tid >= BB * NVV) return;
    int b = tid / NVV;
    int n = tid - b * NVV;
    float w = Vw[tid];
    size_t o = (size_t)tid * 3;
    out[o + 0] = Vp[o + 0] + w * g_Lv[(size_t)(b * 3 + 0) * NVV + n];
    out[o + 1] = Vp[o + 1] + w * g_Lv[(size_t)(b * 3 + 1) * NVV + n];
    out[o + 2] = Vp[o + 2] + w * g_Lv[(size_t)(b * 3 + 2) * NVV + n];
}

// ---------------------------------------------------------------------------
extern "C" void kernel_launch(void* const* d_in, const int* in_sizes, int n_in,
                              void* d_out, int out_size)
{
    const float* Vp  = (const float*)d_in[0];   // V_predict    (B,NV,3)
    const float* L   = (const float*)d_in[1];   // L            (B,E,1)
    const float* Vw  = (const float*)d_in[2];   // V_w          (B,NV,1)
    const float* Vc  = (const float*)d_in[3];   // V_compliance (B,1,1)
    const int*   Cd  = (const int*)  d_in[4];   // C_dist       (E,2)
    const float* Cid = (const float*)d_in[5];   // C_init_d     (E,1)
    const float* Cm  = (const float*)d_in[6];   // C_mtx        (E,NV)

    float* out_vp = (float*)d_out;                         // V_predict_new
    float* out_L  = (float*)d_out + (size_t)BB * NVV * 3;  // L_new

    // 0) zero accumulator
    k_zero<<<(24 * NVV + 255) / 256, 256>>>();

    // 1) edge solve -> M, L_new
    k_edge<<<(BB * EE + 255) / 256, 256>>>(Vp, L, Vw, Vc, Cd, Cid, out_L);

    // 2) tall-skinny GEMM: Lv = M^T @ C_mtx  (persistent, single wave)
    k_gemm<<<GRID_G, GT>>>(Cm);

    // 3) vertex update
    k_epi<<<(BB * NVV + 255) / 256, 256>>>(Vp, Vw, out_vp);
}

// round 12
// speedup vs baseline: 2.4624x; 1.6060x over previous
#include <cuda_runtime.h>
#include <cuda_bf16.h>
#include <cstdint>

// Problem constants (fixed shapes from reference)
#define BB 8
#define NVV 8192
#define EE 32768

typedef unsigned long long ull;

// ---------------------------------------------------------------------------
// Device scratch (no cudaMalloc allowed)
//  - M matrix split to bf16 hi / residual-lo, layout [bc][e], bc = b*3+c
//  - g_Lv: fp32 L_vert accumulator [bc][n]
// ---------------------------------------------------------------------------
__device__ __nv_bfloat16 g_Bhi[24 * EE];   // 1.5 MB
__device__ __nv_bfloat16 g_Blo[24 * EE];   // 1.5 MB
__device__ float         g_Lv[24 * NVV];   // 768 KB

// ---------------------------------------------------------------------------
// Kernel 0: zero the L_vert accumulator
// ---------------------------------------------------------------------------
__global__ void k_zero() {
    int t = blockIdx.x * blockDim.x + threadIdx.x;
    if (t < 24 * NVV) g_Lv[t] = 0.0f;
}

// ---------------------------------------------------------------------------
// Kernel 1: per-(b,e) constraint solve -> L_new + split-bf16 M scratch [bc][e]
// ---------------------------------------------------------------------------
__global__ void k_edge(const float* __restrict__ Vp,     // (B,NV,3)
                       const float* __restrict__ L,      // (B,E,1)
                       const float* __restrict__ Vw,     // (B,NV,1)
                       const float* __restrict__ Vc,     // (B,1,1)
                       const int*   __restrict__ Cd,     // (E,2)
                       const float* __restrict__ Cid,    // (E,1)
                       float*       __restrict__ Lnew)   // (B,E) at d_out + B*NV*3
{
    int tid = blockIdx.x * blockDim.x + threadIdx.x;
    if (tid >= BB * EE) return;
    int b = tid / EE;
    int e = tid - b * EE;

    int i = Cd[2 * e];
    int j = Cd[2 * e + 1];

    const float* pi = Vp + ((size_t)b * NVV + i) * 3;
    const float* pj = Vp + ((size_t)b * NVV + j) * 3;
    float nx = pi[0] - pj[0];
    float ny = pi[1] - pj[1];
    float nz = pi[2] - pj[2];
    float D = sqrtf(nx * nx + ny * ny + nz * nz);
    float C = D - Cid[e];

    float A = Vc[b];
    float S = Vw[b * NVV + i] + Vw[b * NVV + j];
    float Seff = (S == 0.0f) ? __int_as_float(0x7f800000) : S;   // inf where S==0
    float denom = Seff + A;

    float l  = L[tid];
    float ld = (-C - A * l) / denom;    // -> 0 when denom == inf
    Lnew[tid] = l + ld;

    float inv = ld / (D + 1e-8f);       // L_delta * N_norm
    float m0 = inv * nx, m1 = inv * ny, m2 = inv * nz;

#pragma unroll
    for (int c = 0; c < 3; c++) {
        float m = (c == 0) ? m0 : (c == 1) ? m1 : m2;
        size_t o = (size_t)(b * 3 + c) * EE + e;
        __nv_bfloat16 h = __float2bfloat16(m);
        g_Bhi[o] = h;
        g_Blo[o] = __float2bfloat16(m - __bfloat162float(h));
    }
}

// ---------------------------------------------------------------------------
// Kernel 2: Lv[bc][n] += sum_e Cm[e][n] * M[bc][e]   via mma.sync bf16 (HMMA).
//
// fp32 emulation: Cm = Ah + Al, M = Bh + Bl (bf16 hi + bf16 residual);
// D = Ah*Bh + Ah*Bl + Al*Bh (Al*Bl ~2^-18/term dropped).
//
// mma.sync.m16n8k16.row.col: M-dim = n (vertex), N-dim = bc (24 = 3 x n8),
// K = e. Per 32-e chunk:
//  - A: coalesced float4 loads of Cm, in-register split to bf16 hi/lo,
//    stored to SMEM [e][n] with XOR-16B-chunk swizzle; fragments via
//    ldmatrix.x4.trans (conflict-free).
//  - B: 24x32 bf16 hi/lo tiles staged at 80-byte row stride; scalar LDS
//    fragment gather (80B stride -> 32 distinct banks).
//  - per warp: 2 m16-tiles x 3 bc-tiles x 3 products = 18 HMMA per k16.
// Grid: (64 n-tiles of 128, 8 e-segments of 4096) = 512 CTAs ~ one wave.
// Epilogue: fragment atomicAdd into g_Lv.
// ---------------------------------------------------------------------------
#define TCT 128
#define NSEG 8
#define E_PER (EE / NSEG)            // 4096
#define CHUNK 32
#define NCHUNK (E_PER / CHUNK)       // 128
#define BROW 40                      // sB row stride in halves (80 B)

__device__ __forceinline__ uint32_t s2u(const void* p) {
    return (uint32_t)__cvta_generic_to_shared(p);
}

__device__ __forceinline__ void ldsm_x4_t(uint32_t* r, uint32_t addr) {
    asm volatile(
        "ldmatrix.sync.aligned.m8n8.x4.trans.shared.b16 {%0,%1,%2,%3}, [%4];"
        : "=r"(r[0]), "=r"(r[1]), "=r"(r[2]), "=r"(r[3]) : "r"(addr));
}
__device__ __forceinline__ void hmma(float* d, const uint32_t* a,
                                     uint32_t b0, uint32_t b1) {
    asm volatile(
        "mma.sync.aligned.m16n8k16.row.col.f32.bf16.bf16.f32 "
        "{%0,%1,%2,%3}, {%4,%5,%6,%7}, {%8,%9}, {%0,%1,%2,%3};"
        : "+f"(d[0]), "+f"(d[1]), "+f"(d[2]), "+f"(d[3])
        : "r"(a[0]), "r"(a[1]), "r"(a[2]), "r"(a[3]), "r"(b0), "r"(b1));
}
// pack (f_hi16 <- fh, f_lo16 <- fl)
__device__ __forceinline__ uint32_t bf16x2(float fh, float fl) {
    uint32_t w;
    asm("cvt.rn.satfinite.bf16x2.f32 %0, %1, %2;" : "=r"(w) : "f"(fh), "f"(fl));
    return w;
}

__global__ void __launch_bounds__(TCT, 4)
k_gemm_tc(const float* __restrict__ Cm)   // C_mtx (E, NV) row-major
{
    // A tiles: [e][n] bf16, 32 e rows x 128 n cols, 256 B/row, XOR swizzle
    __shared__ alignas(16) unsigned char sAhi[32 * 256];   // 8 KB
    __shared__ alignas(16) unsigned char sAlo[32 * 256];   // 8 KB
    // B tiles: [bc][e] bf16, 24 rows x 32 e + pad, 80 B/row
    __shared__ alignas(16) __nv_bfloat16 sBhi[24 * BROW];  // 1.9 KB
    __shared__ alignas(16) __nv_bfloat16 sBlo[24 * BROW];

    const int t    = threadIdx.x;
    const int warp = t >> 5;
    const int lane = t & 31;
    const int g    = lane >> 2;      // group 0..7
    const int tig  = lane & 3;       // thread-in-group

    const int n0     = blockIdx.x * 128;
    const int e_base = blockIdx.y * E_PER;

    float acc[2][3][4];
#pragma unroll
    for (int mt = 0; mt < 2; mt++)
#pragma unroll
        for (int bt = 0; bt < 3; bt++)
#pragma unroll
            for (int r = 0; r < 4; r++) acc[mt][bt][r] = 0.0f;

    // ldmatrix.trans source addresses (per lane, fixed across chunks):
    // lanes 0-7: k0-7 x m0-7 | 8-15: k0-7 x m8-15 | 16-23: k8-15 x m0-7 |
    // 24-31: k8-15 x m8-15   (m base = warp*32 + mt*16)
    const int li   = lane & 7;
    const int half = (lane >> 3) & 1;
    const int kh   = lane >> 4;

    const int a_nt   = (t & 31) * 4;      // n offset of this thread's float4
    const int a_erow = t >> 5;            // e row 0..3 (stride 4)
    const uint32_t a_c     = (uint32_t)(a_nt >> 3);
    const uint32_t a_inner = (uint32_t)((a_nt & 4) << 1);   // 0 or 8

    for (int ck = 0; ck < NCHUNK; ck++) {
        const int e0 = e_base + ck * CHUNK;

        // ---- stage A: 32e x 128n fp32 -> bf16 hi/lo, swizzled SMEM ----
        {
            const float* base = Cm + (size_t)(e0 + a_erow) * NVV + n0 + a_nt;
#pragma unroll
            for (int i = 0; i < 8; i++) {
                float4 v = __ldcs(reinterpret_cast<const float4*>(
                    base + (size_t)(4 * i) * NVV));
                int e = a_erow + 4 * i;
                uint32_t h01 = bf16x2(v.y, v.x);
                uint32_t h23 = bf16x2(v.w, v.z);
                float r0 = v.x - __uint_as_float(h01 << 16);
                float r1 = v.y - __uint_as_float(h01 & 0xffff0000u);
                float r2 = v.z - __uint_as_float(h23 << 16);
                float r3 = v.w - __uint_as_float(h23 & 0xffff0000u);
                uint32_t l01 = bf16x2(r1, r0);
                uint32_t l23 = bf16x2(r3, r2);
                uint32_t off = (uint32_t)e * 256 +
                               (((a_c ^ (uint32_t)(e & 7)) << 4) | a_inner);
                *reinterpret_cast<uint2*>(sAhi + off) = make_uint2(h01, h23);
                *reinterpret_cast<uint2*>(sAlo + off) = make_uint2(l01, l23);
            }
        }
        // ---- stage B: 24 x 32 bf16 hi/lo ----
        if (t < 96) {
            int bc = t >> 2, part = t & 3;
            const uint4* sh = reinterpret_cast<const uint4*>(
                g_Bhi + (size_t)bc * EE + e0) + part;
            const uint4* sl = reinterpret_cast<const uint4*>(
                g_Blo + (size_t)bc * EE + e0) + part;
            *reinterpret_cast<uint4*>(sBhi + bc * BROW + part * 8) = *sh;
            *reinterpret_cast<uint4*>(sBlo + bc * BROW + part * 8) = *sl;
        }
        __syncthreads();

        // ---- compute: 2 k16 steps ----
#pragma unroll
        for (int ks = 0; ks < 2; ks++) {
            const int ek = ks * 16;
            // B fragments (scalar LDS, conflict-free by 80B row stride)
            uint32_t bh0[3], bh1[3], bl0[3], bl1[3];
#pragma unroll
            for (int bt = 0; bt < 3; bt++) {
                int row = (bt * 8 + g) * BROW;
                bh0[bt] = *reinterpret_cast<const uint32_t*>(sBhi + row + ek + 2 * tig);
                bh1[bt] = *reinterpret_cast<const uint32_t*>(sBhi + row + ek + 8 + 2 * tig);
                bl0[bt] = *reinterpret_cast<const uint32_t*>(sBlo + row + ek + 2 * tig);
                bl1[bt] = *reinterpret_cast<const uint32_t*>(sBlo + row + ek + 8 + 2 * tig);
            }
#pragma unroll
            for (int mt = 0; mt < 2; mt++) {
                const int mb = warp * 32 + mt * 16;
                const int e_loc = ek + kh * 8 + li;
                const uint32_t cc = (uint32_t)((mb >> 3) + half);
                const uint32_t a_off = (uint32_t)e_loc * 256 +
                                       (((cc ^ (uint32_t)(e_loc & 7))) << 4);
                uint32_t ahi[4], alo[4];
                ldsm_x4_t(ahi, s2u(sAhi) + a_off);
                ldsm_x4_t(alo, s2u(sAlo) + a_off);
#pragma unroll
                for (int bt = 0; bt < 3; bt++) {
                    hmma(acc[mt][bt], ahi, bh0[bt], bh1[bt]);
                    hmma(acc[mt][bt], ahi, bl0[bt], bl1[bt]);
                    hmma(acc[mt][bt], alo, bh0[bt], bh1[bt]);
                }
            }
        }
        __syncthreads();
    }

    // ---- epilogue: D fragment -> atomicAdd g_Lv[bc][n] ----
    // c0: (m=g, n=2t) c1: (m=g, n=2t+1) c2: (m=g+8, n=2t) c3: (m=g+8, n=2t+1)
#pragma unroll
    for (int mt = 0; mt < 2; mt++) {
#pragma unroll
        for (int bt = 0; bt < 3; bt++) {
            int n  = n0 + warp * 32 + mt * 16 + g;
            int bc = bt * 8 + 2 * tig;
            atomicAdd(g_Lv + (size_t)bc * NVV + n,           acc[mt][bt][0]);
            atomicAdd(g_Lv + (size_t)(bc + 1) * NVV + n,     acc[mt][bt][1]);
            atomicAdd(g_Lv + (size_t)bc * NVV + n + 8,       acc[mt][bt][2]);
            atomicAdd(g_Lv + (size_t)(bc + 1) * NVV + n + 8, acc[mt][bt][3]);
        }
    }
}

// ---------------------------------------------------------------------------
// Kernel 3: V_predict_new = V_predict + V_w * L_vert
// ---------------------------------------------------------------------------
__global__ void k_epi(const float* __restrict__ Vp,
                      const float* __restrict__ Vw,
                      float*       __restrict__ out)     // (B,NV,3) at d_out
{
    int tid = blockIdx.x * blockDim.x + threadIdx.x;
    if (tid >= BB * NVV) return;
    int b = tid / NVV;
    int n = tid - b * NVV;
    float w = Vw[tid];
    size_t o = (size_t)tid * 3;
    out[o + 0] = Vp[o + 0] + w * g_Lv[(size_t)(b * 3 + 0) * NVV + n];
    out[o + 1] = Vp[o + 1] + w * g_Lv[(size_t)(b * 3 + 1) * NVV + n];
    out[o + 2] = Vp[o + 2] + w * g_Lv[(size_t)(b * 3 + 2) * NVV + n];
}

// ---------------------------------------------------------------------------
extern "C" void kernel_launch(void* const* d_in, const int* in_sizes, int n_in,
                              void* d_out, int out_size)
{
    const float* Vp  = (const float*)d_in[0];   // V_predict    (B,NV,3)
    const float* L   = (const float*)d_in[1];   // L            (B,E,1)
    const float* Vw  = (const float*)d_in[2];   // V_w          (B,NV,1)
    const float* Vc  = (const float*)d_in[3];   // V_compliance (B,1,1)
    const int*   Cd  = (const int*)  d_in[4];   // C_dist       (E,2)
    const float* Cid = (const float*)d_in[5];   // C_init_d     (E,1)
    const float* Cm  = (const float*)d_in[6];   // C_mtx        (E,NV)

    float* out_vp = (float*)d_out;                         // V_predict_new
    float* out_L  = (float*)d_out + (size_t)BB * NVV * 3;  // L_new

    // 0) zero accumulator
    k_zero<<<(24 * NVV + 255) / 256, 256>>>();

    // 1) edge solve -> split-bf16 M, L_new
    k_edge<<<(BB * EE + 255) / 256, 256>>>(Vp, L, Vw, Vc, Cd, Cid, out_L);

    // 2) tensor-core GEMM (mma.sync bf16, split-bf16 fp32 emulation)
    k_gemm_tc<<<dim3(NVV / 128, NSEG), TCT>>>(Cm);

    // 3) vertex update
    k_epi<<<(BB * NVV + 255) / 256, 256>>>(Vp, Vw, out_vp);
}

// round 13
// speedup vs baseline: 2.6627x; 1.0813x over previous
#include <cuda_runtime.h>
#include <cuda_bf16.h>
#include <cstdint>

// Problem constants (fixed shapes from reference)
#define BB 8
#define NVV 8192
#define EE 32768

typedef unsigned long long ull;

// ---------------------------------------------------------------------------
// Device scratch (no cudaMalloc allowed)
//  - M matrix split to bf16 hi / residual-lo, layout [bc][e], bc = b*3+c
//  - g_Lv: fp32 L_vert accumulator [bc][n]
// ---------------------------------------------------------------------------
__device__ __nv_bfloat16 g_Bhi[24 * EE];   // 1.5 MB
__device__ __nv_bfloat16 g_Blo[24 * EE];   // 1.5 MB
__device__ float         g_Lv[24 * NVV];   // 768 KB

#define EDGE_BLOCKS ((BB * EE) / 256)            // 1024
#define ZERO_BLOCKS ((24 * NVV) / 256)           // 768

// ---------------------------------------------------------------------------
// Kernel 1: per-(b,e) constraint solve -> L_new + split-bf16 M scratch [bc][e]
//           (+ fused g_Lv zeroing in trailing blocks)
// ---------------------------------------------------------------------------
__global__ void k_edge(const float* __restrict__ Vp,     // (B,NV,3)
                       const float* __restrict__ L,      // (B,E,1)
                       const float* __restrict__ Vw,     // (B,NV,1)
                       const float* __restrict__ Vc,     // (B,1,1)
                       const int*   __restrict__ Cd,     // (E,2)
                       const float* __restrict__ Cid,    // (E,1)
                       float*       __restrict__ Lnew)   // (B,E) at d_out + B*NV*3
{
    if (blockIdx.x >= EDGE_BLOCKS) {               // fused zero of g_Lv
        int t = (blockIdx.x - EDGE_BLOCKS) * 256 + threadIdx.x;
        g_Lv[t] = 0.0f;
        return;
    }

    int tid = blockIdx.x * 256 + threadIdx.x;
    int b = tid / EE;
    int e = tid - b * EE;

    int i = Cd[2 * e];
    int j = Cd[2 * e + 1];

    const float* pi = Vp + ((size_t)b * NVV + i) * 3;
    const float* pj = Vp + ((size_t)b * NVV + j) * 3;
    float nx = pi[0] - pj[0];
    float ny = pi[1] - pj[1];
    float nz = pi[2] - pj[2];
    float D = sqrtf(nx * nx + ny * ny + nz * nz);
    float C = D - Cid[e];

    float A = Vc[b];
    float S = Vw[b * NVV + i] + Vw[b * NVV + j];
    float Seff = (S == 0.0f) ? __int_as_float(0x7f800000) : S;   // inf where S==0
    float denom = Seff + A;

    float l  = L[tid];
    float ld = (-C - A * l) / denom;    // -> 0 when denom == inf
    Lnew[tid] = l + ld;

    float inv = ld / (D + 1e-8f);       // L_delta * N_norm
    float m0 = inv * nx, m1 = inv * ny, m2 = inv * nz;

#pragma unroll
    for (int c = 0; c < 3; c++) {
        float m = (c == 0) ? m0 : (c == 1) ? m1 : m2;
        size_t o = (size_t)(b * 3 + c) * EE + e;
        __nv_bfloat16 h = __float2bfloat16(m);
        g_Bhi[o] = h;
        g_Blo[o] = __float2bfloat16(m - __bfloat162float(h));
    }
}

// ---------------------------------------------------------------------------
// Kernel 2: Lv[bc][n] += sum_e Cm[e][n] * M[bc][e]   via mma.sync bf16 (HMMA).
//
// fp32 emulation: D = Ah*Bh + Ah*Bl + Al*Bh (Al*Bl dropped).
// v2: software-pipelined DOUBLE BUFFER — next chunk's global loads are issued
// into registers right after the single per-chunk barrier, so LDGs are in
// flight throughout the MMA phase. One __syncthreads per chunk (read@k and
// write@k+2 of the same buffer are separated by the k+1 barrier).
// ---------------------------------------------------------------------------
#define TCT 128
#define NSEG 8
#define E_PER (EE / NSEG)            // 4096
#define CHUNK 32
#define NCHUNK (E_PER / CHUNK)       // 128
#define BROW 40                      // sB row stride in halves (80 B)

__device__ __forceinline__ uint32_t s2u(const void* p) {
    return (uint32_t)__cvta_generic_to_shared(p);
}
__device__ __forceinline__ void ldsm_x4_t(uint32_t* r, uint32_t addr) {
    asm volatile(
        "ldmatrix.sync.aligned.m8n8.x4.trans.shared.b16 {%0,%1,%2,%3}, [%4];"
        : "=r"(r[0]), "=r"(r[1]), "=r"(r[2]), "=r"(r[3]) : "r"(addr));
}
__device__ __forceinline__ void hmma(float* d, const uint32_t* a,
                                     uint32_t b0, uint32_t b1) {
    asm volatile(
        "mma.sync.aligned.m16n8k16.row.col.f32.bf16.bf16.f32 "
        "{%0,%1,%2,%3}, {%4,%5,%6,%7}, {%8,%9}, {%0,%1,%2,%3};"
        : "+f"(d[0]), "+f"(d[1]), "+f"(d[2]), "+f"(d[3])
        : "r"(a[0]), "r"(a[1]), "r"(a[2]), "r"(a[3]), "r"(b0), "r"(b1));
}
__device__ __forceinline__ uint32_t bf16x2(float fh, float fl) {
    uint32_t w;
    asm("cvt.rn.satfinite.bf16x2.f32 %0, %1, %2;" : "=r"(w) : "f"(fh), "f"(fl));
    return w;
}

__global__ void __launch_bounds__(TCT, 4)
k_gemm_tc(const float* __restrict__ Cm)   // C_mtx (E, NV) row-major
{
    // double-buffered A tiles: [e][n] bf16, 32 x 128, 256 B/row, XOR swizzle
    __shared__ alignas(16) unsigned char sAhi[2][32 * 256];   // 16 KB
    __shared__ alignas(16) unsigned char sAlo[2][32 * 256];   // 16 KB
    // double-buffered B tiles: [bc][e] bf16, 24 x 32 + pad, 80 B/row
    __shared__ alignas(16) __nv_bfloat16 sBhi[2][24 * BROW];  // 3.8 KB
    __shared__ alignas(16) __nv_bfloat16 sBlo[2][24 * BROW];

    const int t    = threadIdx.x;
    const int warp = t >> 5;
    const int lane = t & 31;
    const int g    = lane >> 2;
    const int tig  = lane & 3;

    const int n0     = blockIdx.x * 128;
    const int e_base = blockIdx.y * E_PER;

    float acc[2][3][4];
#pragma unroll
    for (int mt = 0; mt < 2; mt++)
#pragma unroll
        for (int bt = 0; bt < 3; bt++)
#pragma unroll
            for (int r = 0; r < 4; r++) acc[mt][bt][r] = 0.0f;

    const int li   = lane & 7;
    const int half = (lane >> 3) & 1;
    const int kh   = lane >> 4;

    const int a_nt   = (t & 31) * 4;      // n offset of this thread's float4
    const int a_erow = t >> 5;            // e row 0..3 (stride 4)
    const uint32_t a_c     = (uint32_t)(a_nt >> 3);
    const uint32_t a_inner = (uint32_t)((a_nt & 4) << 1);   // 0 or 8

    const int b_bc   = t >> 2;            // t<96: bc row
    const int b_part = t & 3;

    const float* a_base = Cm + (size_t)(e_base + a_erow) * NVV + n0 + a_nt;

    // ---- preload chunk 0 into registers ----
    float4 v[8];
#pragma unroll
    for (int i = 0; i < 8; i++)
        v[i] = __ldcs(reinterpret_cast<const float4*>(a_base + (size_t)(4 * i) * NVV));
    uint4 bvh, bvl;
    if (t < 96) {
        bvh = *(reinterpret_cast<const uint4*>(g_Bhi + (size_t)b_bc * EE + e_base) + b_part);
        bvl = *(reinterpret_cast<const uint4*>(g_Blo + (size_t)b_bc * EE + e_base) + b_part);
    }

    int p = 0;
    for (int ck = 0; ck < NCHUNK; ck++) {
        // ---- convert & store registers -> SMEM buffer p ----
#pragma unroll
        for (int i = 0; i < 8; i++) {
            int e = a_erow + 4 * i;
            uint32_t h01 = bf16x2(v[i].y, v[i].x);
            uint32_t h23 = bf16x2(v[i].w, v[i].z);
            float r0 = v[i].x - __uint_as_float(h01 << 16);
            float r1 = v[i].y - __uint_as_float(h01 & 0xffff0000u);
            float r2 = v[i].z - __uint_as_float(h23 << 16);
            float r3 = v[i].w - __uint_as_float(h23 & 0xffff0000u);
            uint32_t l01 = bf16x2(r1, r0);
            uint32_t l23 = bf16x2(r3, r2);
            uint32_t off = (uint32_t)e * 256 +
                           (((a_c ^ (uint32_t)(e & 7)) << 4) | a_inner);
            *reinterpret_cast<uint2*>(&sAhi[p][0] + off) = make_uint2(h01, h23);
            *reinterpret_cast<uint2*>(&sAlo[p][0] + off) = make_uint2(l01, l23);
        }
        if (t < 96) {
            *reinterpret_cast<uint4*>(sBhi[p] + b_bc * BROW + b_part * 8) = bvh;
            *reinterpret_cast<uint4*>(sBlo[p] + b_bc * BROW + b_part * 8) = bvl;
        }
        __syncthreads();

        // ---- issue next chunk's global loads (in flight during compute) ----
        if (ck + 1 < NCHUNK) {
            const float* nb = a_base + (size_t)(ck + 1) * CHUNK * NVV;
#pragma unroll
            for (int i = 0; i < 8; i++)
                v[i] = __ldcs(reinterpret_cast<const float4*>(nb + (size_t)(4 * i) * NVV));
            if (t < 96) {
                int e1 = e_base + (ck + 1) * CHUNK;
                bvh = *(reinterpret_cast<const uint4*>(g_Bhi + (size_t)b_bc * EE + e1) + b_part);
                bvl = *(reinterpret_cast<const uint4*>(g_Blo + (size_t)b_bc * EE + e1) + b_part);
            }
        }

        // ---- compute: 2 k16 steps from buffer p ----
#pragma unroll
        for (int ks = 0; ks < 2; ks++) {
            const int ek = ks * 16;
            uint32_t bh0[3], bh1[3], bl0[3], bl1[3];
#pragma unroll
            for (int bt = 0; bt < 3; bt++) {
                int row = (bt * 8 + g) * BROW;
                bh0[bt] = *reinterpret_cast<const uint32_t*>(sBhi[p] + row + ek + 2 * tig);
                bh1[bt] = *reinterpret_cast<const uint32_t*>(sBhi[p] + row + ek + 8 + 2 * tig);
                bl0[bt] = *reinterpret_cast<const uint32_t*>(sBlo[p] + row + ek + 2 * tig);
                bl1[bt] = *reinterpret_cast<const uint32_t*>(sBlo[p] + row + ek + 8 + 2 * tig);
            }
#pragma unroll
            for (int mt = 0; mt < 2; mt++) {
                const int mb = warp * 32 + mt * 16;
                const int e_loc = ek + kh * 8 + li;
                const uint32_t cc = (uint32_t)((mb >> 3) + half);
                const uint32_t a_off = (uint32_t)e_loc * 256 +
                                       ((cc ^ (uint32_t)(e_loc & 7)) << 4);
                uint32_t ahi[4], alo[4];
                ldsm_x4_t(ahi, s2u(&sAhi[p][0]) + a_off);
                ldsm_x4_t(alo, s2u(&sAlo[p][0]) + a_off);
#pragma unroll
                for (int bt = 0; bt < 3; bt++) {
                    hmma(acc[mt][bt], ahi, bh0[bt], bh1[bt]);
                    hmma(acc[mt][bt], ahi, bl0[bt], bl1[bt]);
                    hmma(acc[mt][bt], alo, bh0[bt], bh1[bt]);
                }
            }
        }
        p ^= 1;
    }

    // ---- epilogue: D fragment -> atomicAdd g_Lv[bc][n] ----
#pragma unroll
    for (int mt = 0; mt < 2; mt++) {
#pragma unroll
        for (int bt = 0; bt < 3; bt++) {
            int n  = n0 + warp * 32 + mt * 16 + g;
            int bc = bt * 8 + 2 * tig;
            atomicAdd(g_Lv + (size_t)bc * NVV + n,           acc[mt][bt][0]);
            atomicAdd(g_Lv + (size_t)(bc + 1) * NVV + n,     acc[mt][bt][1]);
            atomicAdd(g_Lv + (size_t)bc * NVV + n + 8,       acc[mt][bt][2]);
            atomicAdd(g_Lv + (size_t)(bc + 1) * NVV + n + 8, acc[mt][bt][3]);
        }
    }
}

// ---------------------------------------------------------------------------
// Kernel 3: V_predict_new = V_predict + V_w * L_vert
// ---------------------------------------------------------------------------
__global__ void k_epi(const float* __restrict__ Vp,
                      const float* __restrict__ Vw,
                      float*       __restrict__ out)     // (B,NV,3) at d_out
{
    int tid = blockIdx.x * blockDim.x + threadIdx.x;
    if (tid >= BB * NVV) return;
    int b = tid / NVV;
    int n = tid - b * NVV;
    float w = Vw[tid];
    size_t o = (size_t)tid * 3;
    out[o + 0] = Vp[o + 0] + w * g_Lv[(size_t)(b * 3 + 0) * NVV + n];
    out[o + 1] = Vp[o + 1] + w * g_Lv[(size_t)(b * 3 + 1) * NVV + n];
    out[o + 2] = Vp[o + 2] + w * g_Lv[(size_t)(b * 3 + 2) * NVV + n];
}

// ---------------------------------------------------------------------------
extern "C" void kernel_launch(void* const* d_in, const int* in_sizes, int n_in,
                              void* d_out, int out_size)
{
    const float* Vp  = (const float*)d_in[0];   // V_predict    (B,NV,3)
    const float* L   = (const float*)d_in[1];   // L            (B,E,1)
    const float* Vw  = (const float*)d_in[2];   // V_w          (B,NV,1)
    const float* Vc  = (const float*)d_in[3];   // V_compliance (B,1,1)
    const int*   Cd  = (const int*)  d_in[4];   // C_dist       (E,2)
    const float* Cid = (const float*)d_in[5];   // C_init_d     (E,1)
    const float* Cm  = (const float*)d_in[6];   // C_mtx        (E,NV)

    float* out_vp = (float*)d_out;                         // V_predict_new
    float* out_L  = (float*)d_out + (size_t)BB * NVV * 3;  // L_new

    // 1) edge solve -> split-bf16 M, L_new  (+ fused g_Lv zeroing)
    k_edge<<<EDGE_BLOCKS + ZERO_BLOCKS, 256>>>(Vp, L, Vw, Vc, Cd, Cid, out_L);

    // 2) tensor-core GEMM (mma.sync bf16, double-buffered pipeline)
    k_gemm_tc<<<dim3(NVV / 128, NSEG), TCT>>>(Cm);

    // 3) vertex update
    k_epi<<<(BB * NVV + 255) / 256, 256>>>(Vp, Vw, out_vp);
}

// round 14
// speedup vs baseline: 2.8815x; 1.0822x over previous
#include <cuda_runtime.h>
#include <cuda_bf16.h>
#include <cstdint>

// Problem constants (fixed shapes from reference)
#define BB 8
#define NVV 8192
#define EE 32768

typedef unsigned long long ull;

// ---------------------------------------------------------------------------
// Device scratch (no cudaMalloc allowed)
//  - M matrix split to bf16 hi / residual-lo, layout [bc][e], bc = b*3+c
//  - g_Lv: fp32 L_vert accumulator [bc][n]
// ---------------------------------------------------------------------------
__device__ __nv_bfloat16 g_Bhi[24 * EE];   // 1.5 MB
__device__ __nv_bfloat16 g_Blo[24 * EE];   // 1.5 MB
__device__ float         g_Lv[24 * NVV];   // 768 KB

#define EDGE_BLOCKS ((BB * EE) / 256)            // 1024
#define ZERO_BLOCKS ((24 * NVV) / 256)           // 768

// ---------------------------------------------------------------------------
// Kernel 1: per-(b,e) constraint solve -> L_new + split-bf16 M scratch [bc][e]
//           (+ fused g_Lv zeroing in trailing blocks)
// ---------------------------------------------------------------------------
__global__ void k_edge(const float* __restrict__ Vp,     // (B,NV,3)
                       const float* __restrict__ L,      // (B,E,1)
                       const float* __restrict__ Vw,     // (B,NV,1)
                       const float* __restrict__ Vc,     // (B,1,1)
                       const int*   __restrict__ Cd,     // (E,2)
                       const float* __restrict__ Cid,    // (E,1)
                       float*       __restrict__ Lnew)   // (B,E) at d_out + B*NV*3
{
    if (blockIdx.x >= EDGE_BLOCKS) {               // fused zero of g_Lv
        int t = (blockIdx.x - EDGE_BLOCKS) * 256 + threadIdx.x;
        g_Lv[t] = 0.0f;
        return;
    }

    int tid = blockIdx.x * 256 + threadIdx.x;
    int b = tid / EE;
    int e = tid - b * EE;

    int i = Cd[2 * e];
    int j = Cd[2 * e + 1];

    const float* pi = Vp + ((size_t)b * NVV + i) * 3;
    const float* pj = Vp + ((size_t)b * NVV + j) * 3;
    float nx = pi[0] - pj[0];
    float ny = pi[1] - pj[1];
    float nz = pi[2] - pj[2];
    float D = sqrtf(nx * nx + ny * ny + nz * nz);
    float C = D - Cid[e];

    float A = Vc[b];
    float S = Vw[b * NVV + i] + Vw[b * NVV + j];
    float Seff = (S == 0.0f) ? __int_as_float(0x7f800000) : S;   // inf where S==0
    float denom = Seff + A;

    float l  = L[tid];
    float ld = (-C - A * l) / denom;    // -> 0 when denom == inf
    Lnew[tid] = l + ld;

    float inv = ld / (D + 1e-8f);       // L_delta * N_norm
    float m0 = inv * nx, m1 = inv * ny, m2 = inv * nz;

#pragma unroll
    for (int c = 0; c < 3; c++) {
        float m = (c == 0) ? m0 : (c == 1) ? m1 : m2;
        size_t o = (size_t)(b * 3 + c) * EE + e;
        __nv_bfloat16 h = __float2bfloat16(m);
        g_Bhi[o] = h;
        g_Blo[o] = __float2bfloat16(m - __bfloat162float(h));
    }
}

// ---------------------------------------------------------------------------
// Kernel 2: Lv[bc][n] += sum_e Cm[e][n] * M[bc][e]   via mma.sync bf16 (HMMA).
//
// fp32 emulation: D = Ah*Bh + Ah*Bl + Al*Bh (Al*Bl dropped).
// v3: NSEG=32 -> 2048 CTAs of 32 chunks each. Per-CTA duration ~13us, so the
// drain-phase stagger (which left HBM unsaturated for ~25us with 512 coarse
// CTAs) shrinks ~4x. Double-buffered pipeline unchanged.
// ---------------------------------------------------------------------------
#define TCT 128
#define NSEG 32
#define E_PER (EE / NSEG)            // 1024
#define CHUNK 32
#define NCHUNK (E_PER / CHUNK)       // 32
#define BROW 40                      // sB row stride in halves (80 B)

__device__ __forceinline__ uint32_t s2u(const void* p) {
    return (uint32_t)__cvta_generic_to_shared(p);
}
__device__ __forceinline__ void ldsm_x4_t(uint32_t* r, uint32_t addr) {
    asm volatile(
        "ldmatrix.sync.aligned.m8n8.x4.trans.shared.b16 {%0,%1,%2,%3}, [%4];"
        : "=r"(r[0]), "=r"(r[1]), "=r"(r[2]), "=r"(r[3]) : "r"(addr));
}
__device__ __forceinline__ void hmma(float* d, const uint32_t* a,
                                     uint32_t b0, uint32_t b1) {
    asm volatile(
        "mma.sync.aligned.m16n8k16.row.col.f32.bf16.bf16.f32 "
        "{%0,%1,%2,%3}, {%4,%5,%6,%7}, {%8,%9}, {%0,%1,%2,%3};"
        : "+f"(d[0]), "+f"(d[1]), "+f"(d[2]), "+f"(d[3])
        : "r"(a[0]), "r"(a[1]), "r"(a[2]), "r"(a[3]), "r"(b0), "r"(b1));
}
__device__ __forceinline__ uint32_t bf16x2(float fh, float fl) {
    uint32_t w;
    asm("cvt.rn.satfinite.bf16x2.f32 %0, %1, %2;" : "=r"(w) : "f"(fh), "f"(fl));
    return w;
}

__global__ void __launch_bounds__(TCT, 4)
k_gemm_tc(const float* __restrict__ Cm)   // C_mtx (E, NV) row-major
{
    // double-buffered A tiles: [e][n] bf16, 32 x 128, 256 B/row, XOR swizzle
    __shared__ alignas(16) unsigned char sAhi[2][32 * 256];   // 16 KB
    __shared__ alignas(16) unsigned char sAlo[2][32 * 256];   // 16 KB
    // double-buffered B tiles: [bc][e] bf16, 24 x 32 + pad, 80 B/row
    __shared__ alignas(16) __nv_bfloat16 sBhi[2][24 * BROW];  // 3.8 KB
    __shared__ alignas(16) __nv_bfloat16 sBlo[2][24 * BROW];

    const int t    = threadIdx.x;
    const int warp = t >> 5;
    const int lane = t & 31;
    const int g    = lane >> 2;
    const int tig  = lane & 3;

    const int n0     = blockIdx.x * 128;
    const int e_base = blockIdx.y * E_PER;

    float acc[2][3][4];
#pragma unroll
    for (int mt = 0; mt < 2; mt++)
#pragma unroll
        for (int bt = 0; bt < 3; bt++)
#pragma unroll
            for (int r = 0; r < 4; r++) acc[mt][bt][r] = 0.0f;

    const int li   = lane & 7;
    const int half = (lane >> 3) & 1;
    const int kh   = lane >> 4;

    const int a_nt   = (t & 31) * 4;      // n offset of this thread's float4
    const int a_erow = t >> 5;            // e row 0..3 (stride 4)
    const uint32_t a_c     = (uint32_t)(a_nt >> 3);
    const uint32_t a_inner = (uint32_t)((a_nt & 4) << 1);   // 0 or 8

    const int b_bc   = t >> 2;            // t<96: bc row
    const int b_part = t & 3;

    const float* a_base = Cm + (size_t)(e_base + a_erow) * NVV + n0 + a_nt;

    // ---- preload chunk 0 into registers ----
    float4 v[8];
#pragma unroll
    for (int i = 0; i < 8; i++)
        v[i] = __ldcs(reinterpret_cast<const float4*>(a_base + (size_t)(4 * i) * NVV));
    uint4 bvh, bvl;
    if (t < 96) {
        bvh = *(reinterpret_cast<const uint4*>(g_Bhi + (size_t)b_bc * EE + e_base) + b_part);
        bvl = *(reinterpret_cast<const uint4*>(g_Blo + (size_t)b_bc * EE + e_base) + b_part);
    }

    int p = 0;
    for (int ck = 0; ck < NCHUNK; ck++) {
        // ---- convert & store registers -> SMEM buffer p ----
#pragma unroll
        for (int i = 0; i < 8; i++) {
            int e = a_erow + 4 * i;
            uint32_t h01 = bf16x2(v[i].y, v[i].x);
            uint32_t h23 = bf16x2(v[i].w, v[i].z);
            float r0 = v[i].x - __uint_as_float(h01 << 16);
            float r1 = v[i].y - __uint_as_float(h01 & 0xffff0000u);
            float r2 = v[i].z - __uint_as_float(h23 << 16);
            float r3 = v[i].w - __uint_as_float(h23 & 0xffff0000u);
            uint32_t l01 = bf16x2(r1, r0);
            uint32_t l23 = bf16x2(r3, r2);
            uint32_t off = (uint32_t)e * 256 +
                           (((a_c ^ (uint32_t)(e & 7)) << 4) | a_inner);
            *reinterpret_cast<uint2*>(&sAhi[p][0] + off) = make_uint2(h01, h23);
            *reinterpret_cast<uint2*>(&sAlo[p][0] + off) = make_uint2(l01, l23);
        }
        if (t < 96) {
            *reinterpret_cast<uint4*>(sBhi[p] + b_bc * BROW + b_part * 8) = bvh;
            *reinterpret_cast<uint4*>(sBlo[p] + b_bc * BROW + b_part * 8) = bvl;
        }
        __syncthreads();

        // ---- issue next chunk's global loads (in flight during compute) ----
        if (ck + 1 < NCHUNK) {
            const float* nb = a_base + (size_t)(ck + 1) * CHUNK * NVV;
#pragma unroll
            for (int i = 0; i < 8; i++)
                v[i] = __ldcs(reinterpret_cast<const float4*>(nb + (size_t)(4 * i) * NVV));
            if (t < 96) {
                int e1 = e_base + (ck + 1) * CHUNK;
                bvh = *(reinterpret_cast<const uint4*>(g_Bhi + (size_t)b_bc * EE + e1) + b_part);
                bvl = *(reinterpret_cast<const uint4*>(g_Blo + (size_t)b_bc * EE + e1) + b_part);
            }
        }

        // ---- compute: 2 k16 steps from buffer p ----
#pragma unroll
        for (int ks = 0; ks < 2; ks++) {
            const int ek = ks * 16;
            uint32_t bh0[3], bh1[3], bl0[3], bl1[3];
#pragma unroll
            for (int bt = 0; bt < 3; bt++) {
                int row = (bt * 8 + g) * BROW;
                bh0[bt] = *reinterpret_cast<const uint32_t*>(sBhi[p] + row + ek + 2 * tig);
                bh1[bt] = *reinterpret_cast<const uint32_t*>(sBhi[p] + row + ek + 8 + 2 * tig);
                bl0[bt] = *reinterpret_cast<const uint32_t*>(sBlo[p] + row + ek + 2 * tig);
                bl1[bt] = *reinterpret_cast<const uint32_t*>(sBlo[p] + row + ek + 8 + 2 * tig);
            }
#pragma unroll
            for (int mt = 0; mt < 2; mt++) {
                const int mb = warp * 32 + mt * 16;
                const int e_loc = ek + kh * 8 + li;
                const uint32_t cc = (uint32_t)((mb >> 3) + half);
                const uint32_t a_off = (uint32_t)e_loc * 256 +
                                       ((cc ^ (uint32_t)(e_loc & 7)) << 4);
                uint32_t ahi[4], alo[4];
                ldsm_x4_t(ahi, s2u(&sAhi[p][0]) + a_off);
                ldsm_x4_t(alo, s2u(&sAlo[p][0]) + a_off);
#pragma unroll
                for (int bt = 0; bt < 3; bt++) {
                    hmma(acc[mt][bt], ahi, bh0[bt], bh1[bt]);
                    hmma(acc[mt][bt], ahi, bl0[bt], bl1[bt]);
                    hmma(acc[mt][bt], alo, bh0[bt], bh1[bt]);
                }
            }
        }
        p ^= 1;
    }

    // ---- epilogue: D fragment -> atomicAdd g_Lv[bc][n] ----
#pragma unroll
    for (int mt = 0; mt < 2; mt++) {
#pragma unroll
        for (int bt = 0; bt < 3; bt++) {
            int n  = n0 + warp * 32 + mt * 16 + g;
            int bc = bt * 8 + 2 * tig;
            atomicAdd(g_Lv + (size_t)bc * NVV + n,           acc[mt][bt][0]);
            atomicAdd(g_Lv + (size_t)(bc + 1) * NVV + n,     acc[mt][bt][1]);
            atomicAdd(g_Lv + (size_t)bc * NVV + n + 8,       acc[mt][bt][2]);
            atomicAdd(g_Lv + (size_t)(bc + 1) * NVV + n + 8, acc[mt][bt][3]);
        }
    }
}

// ---------------------------------------------------------------------------
// Kernel 3: V_predict_new = V_predict + V_w * L_vert
// ---------------------------------------------------------------------------
__global__ void k_epi(const float* __restrict__ Vp,
                      const float* __restrict__ Vw,
                      float*       __restrict__ out)     // (B,NV,3) at d_out
{
    int tid = blockIdx.x * blockDim.x + threadIdx.x;
    if (tid >= BB * NVV) return;
    int b = tid / NVV;
    int n = tid - b * NVV;
    float w = Vw[tid];
    size_t o = (size_t)tid * 3;
    out[o + 0] = Vp[o + 0] + w * g_Lv[(size_t)(b * 3 + 0) * NVV + n];
    out[o + 1] = Vp[o + 1] + w * g_Lv[(size_t)(b * 3 + 1) * NVV + n];
    out[o + 2] = Vp[o + 2] + w * g_Lv[(size_t)(b * 3 + 2) * NVV + n];
}

// ---------------------------------------------------------------------------
extern "C" void kernel_launch(void* const* d_in, const int* in_sizes, int n_in,
                              void* d_out, int out_size)
{
    const float* Vp  = (const float*)d_in[0];   // V_predict    (B,NV,3)
    const float* L   = (const float*)d_in[1];   // L            (B,E,1)
    const float* Vw  = (const float*)d_in[2];   // V_w          (B,NV,1)
    const float* Vc  = (const float*)d_in[3];   // V_compliance (B,1,1)
    const int*   Cd  = (const int*)  d_in[4];   // C_dist       (E,2)
    const float* Cid = (const float*)d_in[5];   // C_init_d     (E,1)
    const float* Cm  = (const float*)d_in[6];   // C_mtx        (E,NV)

    float* out_vp = (float*)d_out;                         // V_predict_new
    float* out_L  = (float*)d_out + (size_t)BB * NVV * 3;  // L_new

    // 1) edge solve -> split-bf16 M, L_new  (+ fused g_Lv zeroing)
    k_edge<<<EDGE_BLOCKS + ZERO_BLOCKS, 256>>>(Vp, L, Vw, Vc, Cd, Cid, out_L);

    // 2) tensor-core GEMM (mma.sync bf16, double-buffered, fine-grained grid)
    k_gemm_tc<<<dim3(NVV / 128, NSEG), TCT>>>(Cm);

    // 3) vertex update
    k_epi<<<(BB * NVV + 255) / 256, 256>>>(Vp, Vw, out_vp);
}